// round 14
// baseline (speedup 1.0000x reference)
#include <cuda_runtime.h>
#include <cuda_bf16.h>
#include <math.h>

#define NMAX 100000
#define EMAX 1600000
#define ETMAX (EMAX + NMAX)
#define FIN 128
#define HD 64
#define HEADS 8
#define NGRAPH 64
#define NEG_SLOPE 0.2f
#define CSR_BLOCKS 592   // 4 blocks per SM (148 SMs) — co-resident for grid barrier

// ---------------- device scratch ----------------
__device__ __nv_bfloat162 g_h1b[NMAX * 32];  // conv1 projection, bf16 (2 ch/elem)
__device__ float g_h2[NMAX * HD];            // conv1 output after bias+relu
__device__ float g_as1[NMAX * HEADS];
__device__ float g_ad1[NMAX * HEADS];
__device__ float4 g_att2[NMAX];              // (as2, p0, p1, ad2) per node
__device__ int g_csr[ETMAX];                 // src per edge, grouped by dst
__device__ int g_rowptr[NMAX + 1];
__device__ int g_deg[NMAX];
__device__ int g_cur[NMAX];
__device__ int g_bsum[CSR_BLOCKS];
__device__ int g_boff[CSR_BLOCKS];
__device__ float g_ps[NGRAPH * 2];
__device__ int g_cnt[NGRAPH];
__device__ int g_is64;
__device__ volatile unsigned g_barcnt;       // zero-init; reset at end of k_csr

// ---------------- helpers ----------------
__device__ __forceinline__ long long load_idx(const void* p, long long i, int is64) {
    return is64 ? ((const long long*)p)[i] : (long long)((const int*)p)[i];
}
__device__ __forceinline__ float lrelu(float v) {
    return v > 0.f ? v : NEG_SLOPE * v;
}

// software grid barrier: all CSR_BLOCKS blocks co-resident (4/SM).
__device__ __forceinline__ void gridbar(int k) {
    __syncthreads();
    if (threadIdx.x == 0) {
        __threadfence();
        atomicAdd((unsigned*)&g_barcnt, 1u);
        unsigned tgt = (unsigned)k * CSR_BLOCKS;
        while (g_barcnt < tgt) { }
    }
    __syncthreads();
}

// ---------------- kernels ----------------
// (launch #1) int64-vs-int32 detection
__global__ void k_detect(const int* ei32) {
    int t = threadIdx.x;
    int nz = 0;
    for (int i = t; i < 1024; i += 256) nz |= ei32[2 * i + 1];
    nz = __syncthreads_or(nz);
    if (t == 0) g_is64 = nz ? 0 : 1;
}

// (launches #2, #3) no-ops so k_csr is the 4th launch -> profiled by ncu (-s 5 -c 1)
__global__ void k_nop() {}

// (launch #4 — PROFILED next round) entire CSR build, one persistent kernel.
__global__ __launch_bounds__(256) void k_csr(const void* ei, int E, int N) {
    const int bid = blockIdx.x, t = threadIdx.x;
    const int nthr = CSR_BLOCKS * 256;
    const int gt = bid * 256 + t;
    const int ET = E + N;
    const int chunk = (N + CSR_BLOCKS - 1) / CSR_BLOCKS;
    __shared__ int sh[256];
    __shared__ int s_run;

    // phase 0: zero deg + pooled accumulators
    for (int i = gt; i < N; i += nthr) g_deg[i] = 0;
    if (gt < NGRAPH * 2) g_ps[gt] = 0.f;
    if (gt < NGRAPH) g_cnt[gt] = 0;
    gridbar(1);

    int is64 = g_is64;  // written by k_detect (prior launch)

    // phase 1: histogram of dst degrees (edges + self loops), 4x unrolled
    {
        int e = gt;
        for (; e + 3 * nthr < ET; e += 4 * nthr) {
            int e0 = e, e1 = e + nthr, e2 = e + 2 * nthr, e3 = e + 3 * nthr;
            int d0 = (e0 < E) ? (int)load_idx(ei, (long long)E + e0, is64) : (e0 - E);
            int d1 = (e1 < E) ? (int)load_idx(ei, (long long)E + e1, is64) : (e1 - E);
            int d2 = (e2 < E) ? (int)load_idx(ei, (long long)E + e2, is64) : (e2 - E);
            int d3 = (e3 < E) ? (int)load_idx(ei, (long long)E + e3, is64) : (e3 - E);
            atomicAdd(&g_deg[d0], 1);
            atomicAdd(&g_deg[d1], 1);
            atomicAdd(&g_deg[d2], 1);
            atomicAdd(&g_deg[d3], 1);
        }
        for (; e < ET; e += nthr) {
            int d = (e < E) ? (int)load_idx(ei, (long long)E + e, is64) : (e - E);
            atomicAdd(&g_deg[d], 1);
        }
    }
    gridbar(2);

    // phase 2: block-local exclusive scan over this block's contiguous chunk
    {
        int start = bid * chunk;
        int stop = min(N, start + chunk);
        int running = 0;
        for (int base = start; base < stop; base += 256) {
            int idx = base + t;
            int v = (idx < stop) ? __ldcg(&g_deg[idx]) : 0;
            sh[t] = v;
            __syncthreads();
            int val = v;
#pragma unroll
            for (int o = 1; o < 256; o <<= 1) {
                int u = (t >= o) ? sh[t - o] : 0;
                __syncthreads();
                val += u;
                sh[t] = val;
                __syncthreads();
            }
            if (idx < stop) g_rowptr[idx] = running + val - v;
            if (t == 255) s_run = val;
            __syncthreads();
            running += s_run;
            __syncthreads();
        }
        if (t == 0) g_bsum[bid] = running;
    }
    gridbar(3);

    // phase 3: block 0 scans the CSR_BLOCKS per-block totals (multi-batch)
    if (bid == 0) {
        int running = 0;
        for (int base = 0; base < CSR_BLOCKS; base += 256) {
            int idx = base + t;
            int v = (idx < CSR_BLOCKS) ? __ldcg(&g_bsum[idx]) : 0;
            sh[t] = v;
            __syncthreads();
            int val = v;
#pragma unroll
            for (int o = 1; o < 256; o <<= 1) {
                int u = (t >= o) ? sh[t - o] : 0;
                __syncthreads();
                val += u;
                sh[t] = val;
                __syncthreads();
            }
            if (idx < CSR_BLOCKS) g_boff[idx] = running + val - v;
            if (t == 255) s_run = val;
            __syncthreads();
            running += s_run;
            __syncthreads();
        }
        if (t == 0) g_rowptr[N] = running;
    }
    gridbar(4);

    // phase 4: add block offsets; init scatter cursors
    for (int i = gt; i < N; i += nthr) {
        int r = __ldcg(&g_rowptr[i]) + __ldcg(&g_boff[i / chunk]);
        g_rowptr[i] = r;
        g_cur[i] = r;
    }
    gridbar(5);

    // phase 5: scatter edges into CSR slots, 4x unrolled
    {
        int e = gt;
        for (; e + 3 * nthr < ET; e += 4 * nthr) {
            int ee[4] = {e, e + nthr, e + 2 * nthr, e + 3 * nthr};
            int s[4], d[4];
#pragma unroll
            for (int u = 0; u < 4; u++) {
                if (ee[u] < E) {
                    s[u] = (int)load_idx(ei, ee[u], is64);
                    d[u] = (int)load_idx(ei, (long long)E + ee[u], is64);
                } else { s[u] = d[u] = ee[u] - E; }
            }
            int p0 = atomicAdd(&g_cur[d[0]], 1);
            int p1 = atomicAdd(&g_cur[d[1]], 1);
            int p2 = atomicAdd(&g_cur[d[2]], 1);
            int p3 = atomicAdd(&g_cur[d[3]], 1);
            g_csr[p0] = s[0];
            g_csr[p1] = s[1];
            g_csr[p2] = s[2];
            g_csr[p3] = s[3];
        }
        for (; e < ET; e += nthr) {
            int s, d;
            if (e < E) {
                s = (int)load_idx(ei, e, is64);
                d = (int)load_idx(ei, (long long)E + e, is64);
            } else { s = d = e - E; }
            int pos = atomicAdd(&g_cur[d], 1);
            g_csr[pos] = s;
        }
    }

    // completion bookkeeping: last arriver resets barrier counter for next replay
    __syncthreads();
    if (t == 0) {
        __threadfence();
        unsigned old = atomicAdd((unsigned*)&g_barcnt, 1u);
        if (old == 6u * CSR_BLOCKS - 1u) g_barcnt = 0u;
    }
}

// (launch #5) h1 = x @ W1 : 64 nodes x 64 ch per block, 4x4 per thread.
// Epilogue: bf16 store of h1 + per-(node,head) attention dots via lane-pair shfl.
__global__ __launch_bounds__(256) void k_gemm1(const float* __restrict__ x,
                                               const float* __restrict__ W1,
                                               const float* __restrict__ asw,
                                               const float* __restrict__ adw, int N) {
    __shared__ float xs[16][68];
    __shared__ float ws[16][64];
    int tid = threadIdx.x;
    int tx = tid & 15;
    int ty = tid >> 4;
    int n0 = blockIdx.x * 64;
    float acc[4][4] = {};
    for (int k0 = 0; k0 < FIN; k0 += 16) {
#pragma unroll
        for (int r = 0; r < 4; r++) {
            int id = tid + 256 * r;
            int node = id >> 4, kk = id & 15;
            int gn = n0 + node;
            xs[kk][node] = (gn < N) ? x[(size_t)gn * FIN + k0 + kk] : 0.f;
        }
#pragma unroll
        for (int r = 0; r < 4; r++) {
            int id = tid + 256 * r;
            int kk = id >> 6, ch = id & 63;
            ws[kk][ch] = W1[(k0 + kk) * HD + ch];
        }
        __syncthreads();
#pragma unroll
        for (int kk = 0; kk < 16; kk++) {
            float4 xv = *(float4*)&xs[kk][ty * 4];
            float4 wv = *(float4*)&ws[kk][tx * 4];
            float xa[4] = {xv.x, xv.y, xv.z, xv.w};
            float wa[4] = {wv.x, wv.y, wv.z, wv.w};
#pragma unroll
            for (int i = 0; i < 4; i++)
#pragma unroll
                for (int j = 0; j < 4; j++)
                    acc[i][j] = fmaf(xa[i], wa[j], acc[i][j]);
        }
        __syncthreads();
    }
    float aswv[4], adwv[4];
#pragma unroll
    for (int j = 0; j < 4; j++) {
        aswv[j] = asw[tx * 4 + j];
        adwv[j] = adw[tx * 4 + j];
    }
    int hidx = tx >> 1;
#pragma unroll
    for (int i = 0; i < 4; i++) {
        int gn = n0 + ty * 4 + i;
        float ps = 0.f, pd = 0.f;
#pragma unroll
        for (int j = 0; j < 4; j++) {
            ps = fmaf(acc[i][j], aswv[j], ps);
            pd = fmaf(acc[i][j], adwv[j], pd);
        }
        ps += __shfl_xor_sync(0xFFFFFFFFu, ps, 1);
        pd += __shfl_xor_sync(0xFFFFFFFFu, pd, 1);
        if (gn < N) {
            __nv_bfloat162 p0 = __floats2bfloat162_rn(acc[i][0], acc[i][1]);
            __nv_bfloat162 p1 = __floats2bfloat162_rn(acc[i][2], acc[i][3]);
            uint2 u = make_uint2(*(unsigned*)&p0, *(unsigned*)&p1);
            *(uint2*)&g_h1b[(size_t)gn * 32 + tx * 2] = u;
            if ((tx & 1) == 0) {
                g_as1[gn * HEADS + hidx] = ps;
                g_ad1[gn * HEADS + hidx] = pd;
            }
        }
    }
}

// (launch #6) conv1 gather: 2 warps per dst (edge-range split, smem combine),
// lane = 2 channels, 4-edge unroll. Fused softmax-normalize + bias + relu.
__global__ __launch_bounds__(128) void k_gather1(const float* __restrict__ b1, int N) {
    __shared__ float sm[2][3][32];
    int wid = threadIdx.x >> 5;
    int lane = threadIdx.x & 31;
    int dl = wid >> 1;
    int half = wid & 1;
    int d = blockIdx.x * 2 + dl;
    if (d < N) {
        int beg = g_rowptr[d];
        int end = g_rowptr[d + 1];
        int mid = beg + ((end - beg + 1) >> 1);
        int lo = half ? mid : beg;
        int hi = half ? end : mid;
        int hidx = lane >> 2;
        float ad = g_ad1[d * HEADS + hidx];
        float a0 = 0.f, a1 = 0.f, den = 0.f;
        int i = lo;
        for (; i + 3 < hi; i += 4) {
            int s0 = g_csr[i];
            int s1 = g_csr[i + 1];
            int s2 = g_csr[i + 2];
            int s3 = g_csr[i + 3];
            float as0 = g_as1[s0 * HEADS + hidx];
            float as1 = g_as1[s1 * HEADS + hidx];
            float as2 = g_as1[s2 * HEADS + hidx];
            float as3 = g_as1[s3 * HEADS + hidx];
            float2 hv0 = __bfloat1622float2(g_h1b[(size_t)s0 * 32 + lane]);
            float2 hv1 = __bfloat1622float2(g_h1b[(size_t)s1 * 32 + lane]);
            float2 hv2 = __bfloat1622float2(g_h1b[(size_t)s2 * 32 + lane]);
            float2 hv3 = __bfloat1622float2(g_h1b[(size_t)s3 * 32 + lane]);
            float ex0 = __expf(lrelu(as0 + ad));
            float ex1 = __expf(lrelu(as1 + ad));
            float ex2 = __expf(lrelu(as2 + ad));
            float ex3 = __expf(lrelu(as3 + ad));
            den += (ex0 + ex1) + (ex2 + ex3);
            a0 = fmaf(ex0, hv0.x, a0);
            a1 = fmaf(ex0, hv0.y, a1);
            a0 = fmaf(ex1, hv1.x, a0);
            a1 = fmaf(ex1, hv1.y, a1);
            a0 = fmaf(ex2, hv2.x, a0);
            a1 = fmaf(ex2, hv2.y, a1);
            a0 = fmaf(ex3, hv3.x, a0);
            a1 = fmaf(ex3, hv3.y, a1);
        }
        for (; i < hi; i++) {
            int s = g_csr[i];
            float as = g_as1[s * HEADS + hidx];
            float ex = __expf(lrelu(as + ad));
            float2 hv = __bfloat1622float2(g_h1b[(size_t)s * 32 + lane]);
            den += ex;
            a0 = fmaf(ex, hv.x, a0);
            a1 = fmaf(ex, hv.y, a1);
        }
        if (half == 1) {
            sm[dl][0][lane] = a0;
            sm[dl][1][lane] = a1;
            sm[dl][2][lane] = den;
        }
        __syncthreads();
        if (half == 0) {
            a0 += sm[dl][0][lane];
            a1 += sm[dl][1][lane];
            den += sm[dl][2][lane];
            float inv = 1.f / (den + 1e-16f);
            int ch = lane * 2;
            g_h2[(size_t)d * HD + ch]     = fmaxf(a0 * inv + b1[ch], 0.f);
            g_h2[(size_t)d * HD + ch + 1] = fmaxf(a1 * inv + b1[ch + 1], 0.f);
        }
    }
}

// (launch #7) p2 = h2 @ W2 (warp per node) -> packed float4 att2 record
__global__ void k_gemm2(const float* __restrict__ W2, const float* __restrict__ asw,
                        const float* __restrict__ adw, int N) {
    int w = (blockIdx.x * blockDim.x + threadIdx.x) >> 5;
    int lane = threadIdx.x & 31;
    if (w >= N) return;
    float h0 = g_h2[(size_t)w * HD + lane];
    float h1 = g_h2[(size_t)w * HD + 32 + lane];
    float p0 = h0 * W2[2 * lane]     + h1 * W2[2 * (lane + 32)];
    float p1 = h0 * W2[2 * lane + 1] + h1 * W2[2 * (lane + 32) + 1];
#pragma unroll
    for (int o = 16; o; o >>= 1) {
        p0 += __shfl_xor_sync(0xFFFFFFFFu, p0, o);
        p1 += __shfl_xor_sync(0xFFFFFFFFu, p1, o);
    }
    if (lane == 0) {
        float as2 = p0 * asw[0] + p1 * asw[1];
        float ad2 = p0 * adw[0] + p1 * adw[1];
        g_att2[w] = make_float4(as2, p0, p1, ad2);
    }
}

// (launch #8) conv2 gather (warp per dst, one 16B record/edge) + pooling
__global__ __launch_bounds__(128) void k_gather2(const void* bp, int N) {
    int w = (blockIdx.x * 128 + threadIdx.x) >> 5;
    int lane = threadIdx.x & 31;
    if (w >= N) return;
    int d = w;
    int beg = g_rowptr[d];
    int end = g_rowptr[d + 1];
    float ad = g_att2[d].w;
    float den = 0.f, a0 = 0.f, a1 = 0.f;
    for (int i = beg + lane; i < end; i += 32) {
        int s = g_csr[i];
        float4 r = g_att2[s];
        float ex = __expf(lrelu(r.x + ad));
        den += ex;
        a0 = fmaf(ex, r.y, a0);
        a1 = fmaf(ex, r.z, a1);
    }
#pragma unroll
    for (int o = 16; o; o >>= 1) {
        den += __shfl_xor_sync(0xFFFFFFFFu, den, o);
        a0  += __shfl_xor_sync(0xFFFFFFFFu, a0, o);
        a1  += __shfl_xor_sync(0xFFFFFFFFu, a1, o);
    }
    if (lane == 0) {
        float inv = 1.f / (den + 1e-16f);
        int g = (int)load_idx(bp, d, g_is64);
        atomicAdd(&g_ps[2 * g],     a0 * inv);
        atomicAdd(&g_ps[2 * g + 1], a1 * inv);
        atomicAdd(&g_cnt[g], 1);
    }
}

// (launch #9)
__global__ void k_final(const float* __restrict__ b2, float* __restrict__ out) {
    int g = threadIdx.x;
    if (g >= NGRAPH) return;
    float c = fmaxf((float)g_cnt[g], 1.f);
    float s0 = g_ps[2 * g]     / c + b2[0];
    float s1 = g_ps[2 * g + 1] / c + b2[1];
    float m = fmaxf(s0, s1);
    float lse = m + logf(expf(s0 - m) + expf(s1 - m));
    out[2 * g]     = s0 - lse;
    out[2 * g + 1] = s1 - lse;
}

// ---------------- launch ----------------
extern "C" void kernel_launch(void* const* d_in, const int* in_sizes, int n_in,
                              void* d_out, int out_size) {
    const float* x = (const float*)d_in[0];
    const void* ei = d_in[1];
    const void* batch = d_in[2];
    const float* W1 = (const float*)d_in[3];
    const float* as1w = (const float*)d_in[4];
    const float* ad1w = (const float*)d_in[5];
    const float* b1 = (const float*)d_in[6];
    const float* W2 = (const float*)d_in[7];
    const float* as2w = (const float*)d_in[8];
    const float* ad2w = (const float*)d_in[9];
    const float* b2 = (const float*)d_in[10];

    int N = in_sizes[0] / FIN;
    int E = in_sizes[1] / 2;

    // Fork/join resources (created per call; not destroyed — kernel_launch runs
    // only for the correctness call + the single capture call).
    cudaStream_t s2;
    cudaEvent_t e1, e2;
    cudaStreamCreateWithFlags(&s2, cudaStreamNonBlocking);
    cudaEventCreateWithFlags(&e1, cudaEventDisableTiming);
    cudaEventCreateWithFlags(&e2, cudaEventDisableTiming);

    k_detect<<<1, 256>>>((const int*)ei);
    cudaEventRecord(e1, 0);
    cudaStreamWaitEvent(s2, e1, 0);

    // profiling alignment: make k_csr the 4th process launch (ncu -s 5 -c 1)
    k_nop<<<1, 32>>>();
    k_nop<<<1, 32>>>();

    // branch A (s2): single-kernel CSR build (4 blocks/SM)
    k_csr<<<CSR_BLOCKS, 256, 0, s2>>>(ei, E, N);
    cudaEventRecord(e2, s2);

    // branch B (main): projection GEMM + fused attention dots
    k_gemm1<<<(N + 63) / 64, 256>>>(x, W1, as1w, ad1w, N);

    // join + dependent tail
    cudaStreamWaitEvent(0, e2, 0);
    k_gather1<<<(N + 1) / 2, 128>>>(b1, N);
    k_gemm2<<<(N * 32 + 255) / 256, 256>>>(W2, as2w, ad2w, N);
    k_gather2<<<(N + 3) / 4, 128>>>(batch, N);
    k_final<<<1, 64>>>(b2, (float*)d_out);
}

// round 17
// speedup vs baseline: 1.1496x; 1.1496x over previous
#include <cuda_runtime.h>
#include <cuda_bf16.h>
#include <math.h>

#define NMAX 100000
#define EMAX 1600000
#define ETMAX (EMAX + NMAX)
#define FIN 128
#define HD 64
#define HEADS 8
#define NGRAPH 64
#define NEG_SLOPE 0.2f
#define CSR_BLOCKS 148   // one block per SM — co-resident, minimal contention with gemm1

// ---------------- device scratch ----------------
__device__ __nv_bfloat162 g_h1b[NMAX * 32];  // conv1 projection, bf16 (2 ch/elem)
__device__ float g_h2[NMAX * HD];            // conv1 output after bias+relu
__device__ float g_as1[NMAX * HEADS];
__device__ float g_ad1[NMAX * HEADS];
__device__ float4 g_att2[NMAX];              // (as2, p0, p1, ad2) per node
__device__ int g_csr[ETMAX];                 // src per edge, grouped by dst
__device__ int g_rowptr[NMAX + 1];
__device__ int g_deg[NMAX];
__device__ int g_cur[NMAX];
__device__ int g_bsum[CSR_BLOCKS];
__device__ int g_boff[CSR_BLOCKS];
__device__ float g_ps[NGRAPH * 2];
__device__ int g_cnt[NGRAPH];
__device__ int g_is64;
__device__ volatile unsigned g_barcnt;       // zero-init; reset at end of k_csr

// ---------------- helpers ----------------
__device__ __forceinline__ long long load_idx(const void* p, long long i, int is64) {
    return is64 ? ((const long long*)p)[i] : (long long)((const int*)p)[i];
}
__device__ __forceinline__ float lrelu(float v) {
    return v > 0.f ? v : NEG_SLOPE * v;
}

// software grid barrier: all CSR_BLOCKS blocks co-resident (1/SM).
__device__ __forceinline__ void gridbar(int k) {
    __syncthreads();
    if (threadIdx.x == 0) {
        __threadfence();
        atomicAdd((unsigned*)&g_barcnt, 1u);
        unsigned tgt = (unsigned)k * CSR_BLOCKS;
        while (g_barcnt < tgt) { }
    }
    __syncthreads();
}

// ---------------- kernels ----------------
// (launch #1) int64-vs-int32 detection
__global__ void k_detect(const int* ei32) {
    int t = threadIdx.x;
    int nz = 0;
    for (int i = t; i < 1024; i += 256) nz |= ei32[2 * i + 1];
    nz = __syncthreads_or(nz);
    if (t == 0) g_is64 = nz ? 0 : 1;
}

// (launches #2, #3) no-ops so k_gemm1 is the 4th launch -> profiled by ncu (-s 5 -c 1)
__global__ void k_nop() {}

// (launch #5, fork stream) entire CSR build, one persistent kernel.
__global__ __launch_bounds__(256) void k_csr(const void* ei, int E, int N) {
    const int bid = blockIdx.x, t = threadIdx.x;
    const int nthr = CSR_BLOCKS * 256;
    const int gt = bid * 256 + t;
    const int ET = E + N;
    const int chunk = (N + CSR_BLOCKS - 1) / CSR_BLOCKS;
    __shared__ int sh[256];
    __shared__ int s_run;

    // phase 0: zero deg + pooled accumulators
    for (int i = gt; i < N; i += nthr) g_deg[i] = 0;
    if (gt < NGRAPH * 2) g_ps[gt] = 0.f;
    if (gt < NGRAPH) g_cnt[gt] = 0;
    gridbar(1);

    int is64 = g_is64;  // written by k_detect (prior launch)

    // phase 1: histogram of dst degrees (edges + self loops), 4x unrolled
    {
        int e = gt;
        for (; e + 3 * nthr < ET; e += 4 * nthr) {
            int e0 = e, e1 = e + nthr, e2 = e + 2 * nthr, e3 = e + 3 * nthr;
            int d0 = (e0 < E) ? (int)load_idx(ei, (long long)E + e0, is64) : (e0 - E);
            int d1 = (e1 < E) ? (int)load_idx(ei, (long long)E + e1, is64) : (e1 - E);
            int d2 = (e2 < E) ? (int)load_idx(ei, (long long)E + e2, is64) : (e2 - E);
            int d3 = (e3 < E) ? (int)load_idx(ei, (long long)E + e3, is64) : (e3 - E);
            atomicAdd(&g_deg[d0], 1);
            atomicAdd(&g_deg[d1], 1);
            atomicAdd(&g_deg[d2], 1);
            atomicAdd(&g_deg[d3], 1);
        }
        for (; e < ET; e += nthr) {
            int d = (e < E) ? (int)load_idx(ei, (long long)E + e, is64) : (e - E);
            atomicAdd(&g_deg[d], 1);
        }
    }
    gridbar(2);

    // phase 2: block-local exclusive scan over this block's contiguous chunk
    {
        int start = bid * chunk;
        int stop = min(N, start + chunk);
        int running = 0;
        for (int base = start; base < stop; base += 256) {
            int idx = base + t;
            int v = (idx < stop) ? __ldcg(&g_deg[idx]) : 0;
            sh[t] = v;
            __syncthreads();
            int val = v;
#pragma unroll
            for (int o = 1; o < 256; o <<= 1) {
                int u = (t >= o) ? sh[t - o] : 0;
                __syncthreads();
                val += u;
                sh[t] = val;
                __syncthreads();
            }
            if (idx < stop) g_rowptr[idx] = running + val - v;
            if (t == 255) s_run = val;
            __syncthreads();
            running += s_run;
            __syncthreads();
        }
        if (t == 0) g_bsum[bid] = running;
    }
    gridbar(3);

    // phase 3: block 0 scans the per-block totals
    if (bid == 0) {
        int v = (t < CSR_BLOCKS) ? __ldcg(&g_bsum[t]) : 0;
        sh[t] = v;
        __syncthreads();
        int val = v;
#pragma unroll
        for (int o = 1; o < 256; o <<= 1) {
            int u = (t >= o) ? sh[t - o] : 0;
            __syncthreads();
            val += u;
            sh[t] = val;
            __syncthreads();
        }
        if (t < CSR_BLOCKS) g_boff[t] = val - v;
        if (t == CSR_BLOCKS - 1) g_rowptr[N] = val;
    }
    gridbar(4);

    // phase 4: add block offsets; init scatter cursors
    for (int i = gt; i < N; i += nthr) {
        int r = __ldcg(&g_rowptr[i]) + __ldcg(&g_boff[i / chunk]);
        g_rowptr[i] = r;
        g_cur[i] = r;
    }
    gridbar(5);

    // phase 5: scatter edges into CSR slots, 4x unrolled
    {
        int e = gt;
        for (; e + 3 * nthr < ET; e += 4 * nthr) {
            int ee[4] = {e, e + nthr, e + 2 * nthr, e + 3 * nthr};
            int s[4], d[4];
#pragma unroll
            for (int u = 0; u < 4; u++) {
                if (ee[u] < E) {
                    s[u] = (int)load_idx(ei, ee[u], is64);
                    d[u] = (int)load_idx(ei, (long long)E + ee[u], is64);
                } else { s[u] = d[u] = ee[u] - E; }
            }
            int p0 = atomicAdd(&g_cur[d[0]], 1);
            int p1 = atomicAdd(&g_cur[d[1]], 1);
            int p2 = atomicAdd(&g_cur[d[2]], 1);
            int p3 = atomicAdd(&g_cur[d[3]], 1);
            g_csr[p0] = s[0];
            g_csr[p1] = s[1];
            g_csr[p2] = s[2];
            g_csr[p3] = s[3];
        }
        for (; e < ET; e += nthr) {
            int s, d;
            if (e < E) {
                s = (int)load_idx(ei, e, is64);
                d = (int)load_idx(ei, (long long)E + e, is64);
            } else { s = d = e - E; }
            int pos = atomicAdd(&g_cur[d], 1);
            g_csr[pos] = s;
        }
    }

    // completion bookkeeping: last arriver resets barrier counter for next replay
    __syncthreads();
    if (t == 0) {
        __threadfence();
        unsigned old = atomicAdd((unsigned*)&g_barcnt, 1u);
        if (old == 6u * CSR_BLOCKS - 1u) g_barcnt = 0u;
    }
}

// (launch #4 — PROFILED next round) h1 = x @ W1, 64x64 tile, 4x4 per thread.
// Epilogue: bf16 store of h1 + per-(node,head) attention dots via lane-pair shfl.
__global__ __launch_bounds__(256) void k_gemm1(const float* __restrict__ x,
                                               const float* __restrict__ W1,
                                               const float* __restrict__ asw,
                                               const float* __restrict__ adw, int N) {
    __shared__ float xs[16][68];
    __shared__ float ws[16][64];
    int tid = threadIdx.x;
    int tx = tid & 15;
    int ty = tid >> 4;
    int n0 = blockIdx.x * 64;
    float acc[4][4] = {};
    for (int k0 = 0; k0 < FIN; k0 += 16) {
#pragma unroll
        for (int r = 0; r < 4; r++) {
            int id = tid + 256 * r;
            int node = id >> 4, kk = id & 15;
            int gn = n0 + node;
            xs[kk][node] = (gn < N) ? x[(size_t)gn * FIN + k0 + kk] : 0.f;
        }
#pragma unroll
        for (int r = 0; r < 4; r++) {
            int id = tid + 256 * r;
            int kk = id >> 6, ch = id & 63;
            ws[kk][ch] = W1[(k0 + kk) * HD + ch];
        }
        __syncthreads();
#pragma unroll
        for (int kk = 0; kk < 16; kk++) {
            float4 xv = *(float4*)&xs[kk][ty * 4];
            float4 wv = *(float4*)&ws[kk][tx * 4];
            float xa[4] = {xv.x, xv.y, xv.z, xv.w};
            float wa[4] = {wv.x, wv.y, wv.z, wv.w};
#pragma unroll
            for (int i = 0; i < 4; i++)
#pragma unroll
                for (int j = 0; j < 4; j++)
                    acc[i][j] = fmaf(xa[i], wa[j], acc[i][j]);
        }
        __syncthreads();
    }
    float aswv[4], adwv[4];
#pragma unroll
    for (int j = 0; j < 4; j++) {
        aswv[j] = asw[tx * 4 + j];
        adwv[j] = adw[tx * 4 + j];
    }
    int hidx = tx >> 1;
#pragma unroll
    for (int i = 0; i < 4; i++) {
        int gn = n0 + ty * 4 + i;
        float ps = 0.f, pd = 0.f;
#pragma unroll
        for (int j = 0; j < 4; j++) {
            ps = fmaf(acc[i][j], aswv[j], ps);
            pd = fmaf(acc[i][j], adwv[j], pd);
        }
        ps += __shfl_xor_sync(0xFFFFFFFFu, ps, 1);
        pd += __shfl_xor_sync(0xFFFFFFFFu, pd, 1);
        if (gn < N) {
            __nv_bfloat162 p0 = __floats2bfloat162_rn(acc[i][0], acc[i][1]);
            __nv_bfloat162 p1 = __floats2bfloat162_rn(acc[i][2], acc[i][3]);
            uint2 u = make_uint2(*(unsigned*)&p0, *(unsigned*)&p1);
            *(uint2*)&g_h1b[(size_t)gn * 32 + tx * 2] = u;
            if ((tx & 1) == 0) {
                g_as1[gn * HEADS + hidx] = ps;
                g_ad1[gn * HEADS + hidx] = pd;
            }
        }
    }
}

// (launch #6) conv1 gather: 2 warps per dst (edge-range split, smem combine),
// lane = 2 channels, 4-edge unroll. Fused softmax-normalize + bias + relu.
__global__ __launch_bounds__(128) void k_gather1(const float* __restrict__ b1, int N) {
    __shared__ float sm[2][3][32];
    int wid = threadIdx.x >> 5;
    int lane = threadIdx.x & 31;
    int dl = wid >> 1;
    int half = wid & 1;
    int d = blockIdx.x * 2 + dl;
    if (d < N) {
        int beg = g_rowptr[d];
        int end = g_rowptr[d + 1];
        int mid = beg + ((end - beg + 1) >> 1);
        int lo = half ? mid : beg;
        int hi = half ? end : mid;
        int hidx = lane >> 2;
        float ad = g_ad1[d * HEADS + hidx];
        float a0 = 0.f, a1 = 0.f, den = 0.f;
        int i = lo;
        for (; i + 3 < hi; i += 4) {
            int s0 = g_csr[i];
            int s1 = g_csr[i + 1];
            int s2 = g_csr[i + 2];
            int s3 = g_csr[i + 3];
            float as0 = g_as1[s0 * HEADS + hidx];
            float as1 = g_as1[s1 * HEADS + hidx];
            float as2 = g_as1[s2 * HEADS + hidx];
            float as3 = g_as1[s3 * HEADS + hidx];
            float2 hv0 = __bfloat1622float2(g_h1b[(size_t)s0 * 32 + lane]);
            float2 hv1 = __bfloat1622float2(g_h1b[(size_t)s1 * 32 + lane]);
            float2 hv2 = __bfloat1622float2(g_h1b[(size_t)s2 * 32 + lane]);
            float2 hv3 = __bfloat1622float2(g_h1b[(size_t)s3 * 32 + lane]);
            float ex0 = __expf(lrelu(as0 + ad));
            float ex1 = __expf(lrelu(as1 + ad));
            float ex2 = __expf(lrelu(as2 + ad));
            float ex3 = __expf(lrelu(as3 + ad));
            den += (ex0 + ex1) + (ex2 + ex3);
            a0 = fmaf(ex0, hv0.x, a0);
            a1 = fmaf(ex0, hv0.y, a1);
            a0 = fmaf(ex1, hv1.x, a0);
            a1 = fmaf(ex1, hv1.y, a1);
            a0 = fmaf(ex2, hv2.x, a0);
            a1 = fmaf(ex2, hv2.y, a1);
            a0 = fmaf(ex3, hv3.x, a0);
            a1 = fmaf(ex3, hv3.y, a1);
        }
        for (; i < hi; i++) {
            int s = g_csr[i];
            float as = g_as1[s * HEADS + hidx];
            float ex = __expf(lrelu(as + ad));
            float2 hv = __bfloat1622float2(g_h1b[(size_t)s * 32 + lane]);
            den += ex;
            a0 = fmaf(ex, hv.x, a0);
            a1 = fmaf(ex, hv.y, a1);
        }
        if (half == 1) {
            sm[dl][0][lane] = a0;
            sm[dl][1][lane] = a1;
            sm[dl][2][lane] = den;
        }
        __syncthreads();
        if (half == 0) {
            a0 += sm[dl][0][lane];
            a1 += sm[dl][1][lane];
            den += sm[dl][2][lane];
            float inv = 1.f / (den + 1e-16f);
            int ch = lane * 2;
            g_h2[(size_t)d * HD + ch]     = fmaxf(a0 * inv + b1[ch], 0.f);
            g_h2[(size_t)d * HD + ch + 1] = fmaxf(a1 * inv + b1[ch + 1], 0.f);
        }
    }
}

// (launch #7) p2 = h2 @ W2 (warp per node) -> packed float4 att2 record
__global__ void k_gemm2(const float* __restrict__ W2, const float* __restrict__ asw,
                        const float* __restrict__ adw, int N) {
    int w = (blockIdx.x * blockDim.x + threadIdx.x) >> 5;
    int lane = threadIdx.x & 31;
    if (w >= N) return;
    float h0 = g_h2[(size_t)w * HD + lane];
    float h1 = g_h2[(size_t)w * HD + 32 + lane];
    float p0 = h0 * W2[2 * lane]     + h1 * W2[2 * (lane + 32)];
    float p1 = h0 * W2[2 * lane + 1] + h1 * W2[2 * (lane + 32) + 1];
#pragma unroll
    for (int o = 16; o; o >>= 1) {
        p0 += __shfl_xor_sync(0xFFFFFFFFu, p0, o);
        p1 += __shfl_xor_sync(0xFFFFFFFFu, p1, o);
    }
    if (lane == 0) {
        float as2 = p0 * asw[0] + p1 * asw[1];
        float ad2 = p0 * adw[0] + p1 * adw[1];
        g_att2[w] = make_float4(as2, p0, p1, ad2);
    }
}

// (launch #8) conv2 gather (warp per dst, one 16B record/edge) + pooling
__global__ __launch_bounds__(128) void k_gather2(const void* bp, int N) {
    int w = (blockIdx.x * 128 + threadIdx.x) >> 5;
    int lane = threadIdx.x & 31;
    if (w >= N) return;
    int d = w;
    int beg = g_rowptr[d];
    int end = g_rowptr[d + 1];
    float ad = g_att2[d].w;
    float den = 0.f, a0 = 0.f, a1 = 0.f;
    for (int i = beg + lane; i < end; i += 32) {
        int s = g_csr[i];
        float4 r = g_att2[s];
        float ex = __expf(lrelu(r.x + ad));
        den += ex;
        a0 = fmaf(ex, r.y, a0);
        a1 = fmaf(ex, r.z, a1);
    }
#pragma unroll
    for (int o = 16; o; o >>= 1) {
        den += __shfl_xor_sync(0xFFFFFFFFu, den, o);
        a0  += __shfl_xor_sync(0xFFFFFFFFu, a0, o);
        a1  += __shfl_xor_sync(0xFFFFFFFFu, a1, o);
    }
    if (lane == 0) {
        float inv = 1.f / (den + 1e-16f);
        int g = (int)load_idx(bp, d, g_is64);
        atomicAdd(&g_ps[2 * g],     a0 * inv);
        atomicAdd(&g_ps[2 * g + 1], a1 * inv);
        atomicAdd(&g_cnt[g], 1);
    }
}

// (launch #9)
__global__ void k_final(const float* __restrict__ b2, float* __restrict__ out) {
    int g = threadIdx.x;
    if (g >= NGRAPH) return;
    float c = fmaxf((float)g_cnt[g], 1.f);
    float s0 = g_ps[2 * g]     / c + b2[0];
    float s1 = g_ps[2 * g + 1] / c + b2[1];
    float m = fmaxf(s0, s1);
    float lse = m + logf(expf(s0 - m) + expf(s1 - m));
    out[2 * g]     = s0 - lse;
    out[2 * g + 1] = s1 - lse;
}

// ---------------- launch ----------------
extern "C" void kernel_launch(void* const* d_in, const int* in_sizes, int n_in,
                              void* d_out, int out_size) {
    const float* x = (const float*)d_in[0];
    const void* ei = d_in[1];
    const void* batch = d_in[2];
    const float* W1 = (const float*)d_in[3];
    const float* as1w = (const float*)d_in[4];
    const float* ad1w = (const float*)d_in[5];
    const float* b1 = (const float*)d_in[6];
    const float* W2 = (const float*)d_in[7];
    const float* as2w = (const float*)d_in[8];
    const float* ad2w = (const float*)d_in[9];
    const float* b2 = (const float*)d_in[10];

    int N = in_sizes[0] / FIN;
    int E = in_sizes[1] / 2;

    // Fork/join resources (created per call; not destroyed — kernel_launch runs
    // only for the correctness call + the single capture call).
    cudaStream_t s2;
    cudaEvent_t e1, e2;
    cudaStreamCreateWithFlags(&s2, cudaStreamNonBlocking);
    cudaEventCreateWithFlags(&e1, cudaEventDisableTiming);
    cudaEventCreateWithFlags(&e2, cudaEventDisableTiming);

    k_detect<<<1, 256>>>((const int*)ei);
    cudaEventRecord(e1, 0);
    cudaStreamWaitEvent(s2, e1, 0);

    // profiling alignment: k_gemm1 is the 4th process launch (ncu -s 5 -c 1)
    k_nop<<<1, 32>>>();
    k_nop<<<1, 32>>>();

    // branch B (main): projection GEMM + fused attention dots (launch #4)
    k_gemm1<<<(N + 63) / 64, 256>>>(x, W1, as1w, ad1w, N);

    // branch A (s2): single-kernel CSR build (1 block/SM — R13 config)
    k_csr<<<CSR_BLOCKS, 256, 0, s2>>>(ei, E, N);
    cudaEventRecord(e2, s2);

    // join + dependent tail
    cudaStreamWaitEvent(0, e2, 0);
    k_gather1<<<(N + 1) / 2, 128>>>(b1, N);
    k_gemm2<<<(N * 32 + 255) / 256, 256>>>(W2, as2w, ad2w, N);
    k_gather2<<<(N + 3) / 4, 128>>>(batch, N);
    k_final<<<1, 64>>>(b2, (float*)d_out);
}